// round 8
// baseline (speedup 1.0000x reference)
#include <cuda_runtime.h>

typedef unsigned long long ull;

#define THREADS 256
#define SPC     32            // samples per CTA
#define NBLK    256           // 8192 / 32
#define DT      0.1f
#define HDT     0.05f
#define LOG2PI  1.83787706640934548356f

// Interleaved weight matrix: WG[j][k] = (W2[j,k], H[j,k]) packed as f32x2,
// where H[j][k] = W2[j][k] * sum_i W1[i][j]*W3[k][i]  (divergence matrix).
__device__ ull g_WG[256 * 256];

// ---------------- packed f32x2 helpers ----------------
__device__ __forceinline__ ull pack2(float lo, float hi) {
    ull v;
    asm("mov.b64 %0, {%1,%2};" : "=l"(v)
        : "r"(__float_as_uint(lo)), "r"(__float_as_uint(hi)));
    return v;
}
__device__ __forceinline__ void unpack2(ull v, float& lo, float& hi) {
    unsigned a, b;
    asm("mov.b64 {%0,%1}, %2;" : "=r"(a), "=r"(b) : "l"(v));
    lo = __uint_as_float(a); hi = __uint_as_float(b);
}
__device__ __forceinline__ ull fma2(ull a, ull b, ull c) {
    ull d;
    asm("fma.rn.f32x2 %0, %1, %2, %3;" : "=l"(d) : "l"(a), "l"(b), "l"(c));
    return d;
}

// ---------------- shared-memory layout (float offsets) ----------------
#define OFF_W1T 0        // [j][0..15]=W1 z-rows, [16]=W1 t-row, [17]=b1; stride 20 -> 5120
#define OFF_B2  5120     // 256
#define OFF_W3  5376     // W3[k*16+i] -> 4096
#define OFF_B3  9472     // 16
#define OFF_Z   9488     // z_eval [s*17+i] -> 544
#define OFF_HD  10032    // (h1,d1) ull pairs [j*32+s] (16384 floats); ALIASED as h2[s*256+k] later
#define OFF_WD  26416    // per-warp div partials [w*32+s] (256)
#define OFF_DV  26672    // div[s] (32)
#define SMEM_FLOATS 26704
#define SMEM_BYTES (SMEM_FLOATS * 4)

// ---------------- precompute interleaved WG ----------------
__global__ void comp_WG(const float* __restrict__ W1,
                        const float* __restrict__ W2,
                        const float* __restrict__ W3) {
    int j = blockIdx.x;      // 0..255
    int k = threadIdx.x;     // 0..255
    float g = 0.0f;
#pragma unroll
    for (int i = 0; i < 16; i++)
        g = fmaf(W1[i * 256 + j], W3[k * 16 + i], g);
    float w = W2[j * 256 + k];
    g_WG[j * 256 + k] = pack2(w, g * w);
}

// ---------------- main CNF kernel ----------------
__global__ __launch_bounds__(THREADS, 2)
void cnf_kernel(const float* __restrict__ x,
                const float* __restrict__ W1, const float* __restrict__ b1,
                const float* __restrict__ W2, const float* __restrict__ b2,
                const float* __restrict__ W3, const float* __restrict__ b3,
                float* __restrict__ out) {
    extern __shared__ float sm[];
    ull* hdp = (ull*)(sm + OFF_HD);
    const int tid  = threadIdx.x;
    const int lane = tid & 31;
    const int warp = tid >> 5;

    // ---- stage weights into shared ----
#pragma unroll
    for (int i = 0; i < 17; i++)
        sm[OFF_W1T + tid * 20 + i] = W1[i * 256 + tid];
    sm[OFF_W1T + tid * 20 + 17] = b1[tid];
    sm[OFF_B2 + tid] = b2[tid];
    for (int q = tid; q < 4096; q += THREADS) sm[OFF_W3 + q] = W3[q];
    if (tid < 16) sm[OFF_B3 + tid] = b3[tid];

    // ---- RK4 state mapping (phases A/C2): thread t -> sample s=t>>3, comps (i0,i0+1) ----
    const int s  = tid >> 3;
    const int i0 = (tid & 7) << 1;
    const int gid = blockIdx.x * SPC + s;
    float z0a = x[gid * 16 + i0];
    float z0b = x[gid * 16 + i0 + 1];
    sm[OFF_Z + s * 17 + i0]     = z0a;
    sm[OFF_Z + s * 17 + i0 + 1] = z0b;
    float ka = 0.0f, kb = 0.0f;
    float divsum = 0.0f;

    // ---- phase-B micro-tile mapping: warp -> 32-k block; lane = sq*8 + kq ----
    const int kq = lane & 7;          // k group of 4
    const int sq = lane >> 3;         // sample group of 8
    const int k0 = (warp << 5) + (kq << 2);
    const int s0 = sq << 3;           // first of 8 samples
    __syncthreads();

    for (int st = 0; st < 10; ++st) {
        const float tn = (float)st * DT;
#pragma unroll 1
        for (int sub = 0; sub < 4; ++sub) {
            const float te = tn + ((sub == 0) ? 0.0f : ((sub == 3) ? DT : HDT));

            // ======== Phase A: layer 1. warp -> j range, lane -> sample ========
            {
                float zr[16];
#pragma unroll
                for (int i = 0; i < 16; i++) zr[i] = sm[OFF_Z + lane * 17 + i];
                const int jbase = warp << 5;
#pragma unroll 4
                for (int jj = 0; jj < 32; jj++) {
                    const int j = jbase + jj;
                    const float* wr = sm + OFF_W1T + j * 20;
                    float4 w0 = *(const float4*)(wr);
                    float4 w1v = *(const float4*)(wr + 4);
                    float4 w2v = *(const float4*)(wr + 8);
                    float4 w3v = *(const float4*)(wr + 12);
                    float2 tb = *(const float2*)(wr + 16);
                    float a = fmaf(te, tb.x, tb.y);
                    a = fmaf(zr[0],  w0.x, a);  a = fmaf(zr[1],  w0.y, a);
                    a = fmaf(zr[2],  w0.z, a);  a = fmaf(zr[3],  w0.w, a);
                    a = fmaf(zr[4],  w1v.x, a); a = fmaf(zr[5],  w1v.y, a);
                    a = fmaf(zr[6],  w1v.z, a); a = fmaf(zr[7],  w1v.w, a);
                    a = fmaf(zr[8],  w2v.x, a); a = fmaf(zr[9],  w2v.y, a);
                    a = fmaf(zr[10], w2v.z, a); a = fmaf(zr[11], w2v.w, a);
                    a = fmaf(zr[12], w3v.x, a); a = fmaf(zr[13], w3v.y, a);
                    a = fmaf(zr[14], w3v.z, a); a = fmaf(zr[15], w3v.w, a);
                    float e  = __expf(-a);
                    float sg = __fdividef(1.0f, 1.0f + e);
                    float h  = a * sg;                      // silu
                    float d  = fmaf(h, 1.0f - sg, sg);      // silu'
                    hdp[j * 32 + lane] = pack2(h, d);       // interleaved (h,d)
                }
            }
            __syncthreads();

            // ======== Phase B: ONE fused f32x2 GEMM stream ========
            // acc[sp*4+kk] lanes: lo = a2[s,k] (h1·W2), hi = u[s,k] (d1·H)
            ull acc[32];
            {
                const float4 b2v = *(const float4*)(sm + OFF_B2 + k0);
                const ull bi[4] = { pack2(b2v.x, 0.0f), pack2(b2v.y, 0.0f),
                                    pack2(b2v.z, 0.0f), pack2(b2v.w, 0.0f) };
#pragma unroll
                for (int sp = 0; sp < 8; sp++) {
                    acc[sp * 4 + 0] = bi[0]; acc[sp * 4 + 1] = bi[1];
                    acc[sp * 4 + 2] = bi[2]; acc[sp * 4 + 3] = bi[3];
                }
                const ull* wgp = g_WG + k0;
#pragma unroll 1
                for (int jb = 0; jb < 256; jb += 2) {
                    ulonglong2 wA0 = __ldg((const ulonglong2*)(wgp + (jb << 8)));
                    ulonglong2 wA1 = __ldg((const ulonglong2*)(wgp + (jb << 8) + 2));
                    ulonglong2 wB0 = __ldg((const ulonglong2*)(wgp + ((jb + 1) << 8)));
                    ulonglong2 wB1 = __ldg((const ulonglong2*)(wgp + ((jb + 1) << 8) + 2));
#pragma unroll
                    for (int u = 0; u < 2; u++) {
                        const ulonglong2* hp =
                            (const ulonglong2*)(hdp + ((jb + u) << 5) + s0);
                        ulonglong2 h01 = hp[0], h23 = hp[1];
                        ulonglong2 h45 = hp[2], h67 = hp[3];
                        const ull hs[8] = {h01.x, h01.y, h23.x, h23.y,
                                           h45.x, h45.y, h67.x, h67.y};
                        const ull wk[4] = {
                            u ? wB0.x : wA0.x, u ? wB0.y : wA0.y,
                            u ? wB1.x : wA1.x, u ? wB1.y : wA1.y };
#pragma unroll
                        for (int sp = 0; sp < 8; sp++) {
                            acc[sp * 4 + 0] = fma2(hs[sp], wk[0], acc[sp * 4 + 0]);
                            acc[sp * 4 + 1] = fma2(hs[sp], wk[1], acc[sp * 4 + 1]);
                            acc[sp * 4 + 2] = fma2(hs[sp], wk[2], acc[sp * 4 + 2]);
                            acc[sp * 4 + 3] = fma2(hs[sp], wk[3], acc[sp * 4 + 3]);
                        }
                    }
                }
            }

            // ======== Phase C1: silu(a2), div partial dp = sum_k u*silu'(a2) ========
            {
                float dps[8];
#pragma unroll
                for (int sp = 0; sp < 8; sp++) {
                    dps[sp] = 0.0f;
                    float hk[4];
#pragma unroll
                    for (int kk = 0; kk < 4; kk++) {
                        float a, uu;
                        unpack2(acc[sp * 4 + kk], a, uu);
                        float e = __expf(-a);
                        float g = __fdividef(1.0f, 1.0f + e);
                        float h = a * g;
                        float d2 = fmaf(h, 1.0f - g, g);
                        hk[kk] = h;
                        dps[sp] = fmaf(uu, d2, dps[sp]);
                    }
                    acc[sp * 4 + 0] = pack2(hk[0], hk[1]);   // keep h2 packed by k-pair
                    acc[sp * 4 + 1] = pack2(hk[2], hk[3]);
                }
                // reduce each sample's partial over the 8 kq lanes (lane bits 0..2)
#pragma unroll
                for (int sp = 0; sp < 8; sp++) {
                    dps[sp] += __shfl_xor_sync(0xffffffffu, dps[sp], 1);
                    dps[sp] += __shfl_xor_sync(0xffffffffu, dps[sp], 2);
                    dps[sp] += __shfl_xor_sync(0xffffffffu, dps[sp], 4);
                }
                if (kq == 0) {
#pragma unroll
                    for (int sp = 0; sp < 8; sp++)
                        sm[OFF_WD + warp * 32 + s0 + sp] = dps[sp];
                }
            }
            __syncthreads();   // phase-B readers of hd done; WD visible

            // ======== h2 store ([s][256]) + cross-warp div reduce ========
            {
#pragma unroll
                for (int sp = 0; sp < 8; sp++) {
                    ulonglong2 v;
                    v.x = acc[sp * 4 + 0];
                    v.y = acc[sp * 4 + 1];
                    *(ulonglong2*)(sm + OFF_HD + (s0 + sp) * 256 + k0) = v;
                }
                if (tid < 32) {
                    float dv = 0.0f;
#pragma unroll
                    for (int w = 0; w < 8; w++) dv += sm[OFF_WD + w * 32 + tid];
                    sm[OFF_DV + tid] = dv;
                }
            }
            __syncthreads();

            // ======== Phase C2: layer 3 + RK4 update. thread -> (s, i0) ========
            {
                ull fz = pack2(sm[OFF_B3 + i0], sm[OFF_B3 + i0 + 1]);
                const float* h2r = sm + OFF_HD + s * 256;
#pragma unroll 4
                for (int k = 0; k < 256; k += 4) {
                    float4 hq = *(const float4*)(h2r + k);
                    fz = fma2(pack2(hq.x, hq.x), *(const ull*)(sm + OFF_W3 + (k + 0) * 16 + i0), fz);
                    fz = fma2(pack2(hq.y, hq.y), *(const ull*)(sm + OFF_W3 + (k + 1) * 16 + i0), fz);
                    fz = fma2(pack2(hq.z, hq.z), *(const ull*)(sm + OFF_W3 + (k + 2) * 16 + i0), fz);
                    fz = fma2(pack2(hq.w, hq.w), *(const ull*)(sm + OFF_W3 + (k + 3) * 16 + i0), fz);
                }
                float f0, f1;
                unpack2(fz, f0, f1);
                const float wgt = (sub == 1 || sub == 2) ? 2.0f : 1.0f;
                ka = fmaf(wgt, f0, ka);
                kb = fmaf(wgt, f1, kb);
                if ((tid & 7) == 0) divsum = fmaf(wgt, sm[OFF_DV + s], divsum);
                if (sub < 3) {
                    const float c = (sub == 2) ? DT : HDT;
                    sm[OFF_Z + s * 17 + i0]     = fmaf(c, f0, z0a);
                    sm[OFF_Z + s * 17 + i0 + 1] = fmaf(c, f1, z0b);
                } else {
                    z0a = fmaf(DT / 6.0f, ka, z0a);
                    z0b = fmaf(DT / 6.0f, kb, z0b);
                    ka = 0.0f; kb = 0.0f;
                    sm[OFF_Z + s * 17 + i0]     = z0a;
                    sm[OFF_Z + s * 17 + i0 + 1] = z0b;
                }
            }
            __syncthreads();
        }
    }

    // ---- final: logpz - logp1 ----
    float ss = z0a * z0a + z0b * z0b;
    ss += __shfl_xor_sync(0xffffffffu, ss, 1);
    ss += __shfl_xor_sync(0xffffffffu, ss, 2);
    ss += __shfl_xor_sync(0xffffffffu, ss, 4);
    if ((tid & 7) == 0)
        out[gid] = -0.5f * (ss + 16.0f * LOG2PI) + (DT / 6.0f) * divsum;
}

extern "C" void kernel_launch(void* const* d_in, const int* in_sizes, int n_in,
                              void* d_out, int out_size) {
    const float* x  = (const float*)d_in[0];
    const float* W1 = (const float*)d_in[1];
    const float* b1 = (const float*)d_in[2];
    const float* W2 = (const float*)d_in[3];
    const float* b2 = (const float*)d_in[4];
    const float* W3 = (const float*)d_in[5];
    const float* b3 = (const float*)d_in[6];
    float* out = (float*)d_out;

    comp_WG<<<256, 256>>>(W1, W2, W3);

    cudaFuncSetAttribute(cnf_kernel, cudaFuncAttributeMaxDynamicSharedMemorySize,
                         SMEM_BYTES);
    cnf_kernel<<<NBLK, THREADS, SMEM_BYTES>>>(x, W1, b1, W2, b2, W3, b3, out);
}

// round 9
// speedup vs baseline: 1.6468x; 1.6468x over previous
#include <cuda_runtime.h>

typedef unsigned long long ull;

#define THREADS 256
#define SPC     32            // samples per CTA
#define NBLK    256           // 8192 / 32
#define DT      0.1f
#define HDT     0.05f
#define LOG2PI  1.83787706640934548356f

// Interleaved weight matrix: WG[j][k] = (W2[j,k], H[j,k]) packed as f32x2,
// where H[j][k] = W2[j][k] * sum_i W1[i][j]*W3[k][i]  (divergence matrix).
__device__ ull g_WG[256 * 256];

// ---------------- packed f32x2 helpers ----------------
__device__ __forceinline__ ull pack2(float lo, float hi) {
    ull v;
    asm("mov.b64 %0, {%1,%2};" : "=l"(v)
        : "r"(__float_as_uint(lo)), "r"(__float_as_uint(hi)));
    return v;
}
__device__ __forceinline__ void unpack2(ull v, float& lo, float& hi) {
    unsigned a, b;
    asm("mov.b64 {%0,%1}, %2;" : "=r"(a), "=r"(b) : "l"(v));
    lo = __uint_as_float(a); hi = __uint_as_float(b);
}
__device__ __forceinline__ ull fma2(ull a, ull b, ull c) {
    ull d;
    asm("fma.rn.f32x2 %0, %1, %2, %3;" : "=l"(d) : "l"(a), "l"(b), "l"(c));
    return d;
}

// ---------------- shared-memory layout (float offsets) ----------------
#define OFF_W1T 0        // [j][0..15]=W1 z-rows, [16]=W1 t-row, [17]=b1; stride 20 -> 5120
#define OFF_B2  5120     // 256
#define OFF_W3  5376     // W3[k*16+i] -> 4096
#define OFF_B3  9472     // 16
#define OFF_Z   9488     // z_eval [s*17+i] -> 544
#define OFF_HD  10032    // (h1,d1) ull pairs [j*32+s] (16384 floats); ALIASED as h2[s*256+k] later
#define OFF_WD  26416    // per-warp div partials [w*32+s] (256)
#define OFF_DV  26672    // div[s] (32)
#define SMEM_FLOATS 26704
#define SMEM_BYTES (SMEM_FLOATS * 4)

// ---------------- precompute interleaved WG ----------------
__global__ void comp_WG(const float* __restrict__ W1,
                        const float* __restrict__ W2,
                        const float* __restrict__ W3) {
    int j = blockIdx.x;      // 0..255
    int k = threadIdx.x;     // 0..255
    float g = 0.0f;
#pragma unroll
    for (int i = 0; i < 16; i++)
        g = fmaf(W1[i * 256 + j], W3[k * 16 + i], g);
    float w = W2[j * 256 + k];
    g_WG[j * 256 + k] = pack2(w, g * w);
}

// ---------------- main CNF kernel ----------------
__global__ __launch_bounds__(THREADS, 2)
void cnf_kernel(const float* __restrict__ x,
                const float* __restrict__ W1, const float* __restrict__ b1,
                const float* __restrict__ W2, const float* __restrict__ b2,
                const float* __restrict__ W3, const float* __restrict__ b3,
                float* __restrict__ out) {
    extern __shared__ float sm[];
    ull* hdp = (ull*)(sm + OFF_HD);
    const int tid  = threadIdx.x;
    const int lane = tid & 31;
    const int warp = tid >> 5;

    // ---- stage weights into shared ----
#pragma unroll
    for (int i = 0; i < 17; i++)
        sm[OFF_W1T + tid * 20 + i] = W1[i * 256 + tid];
    sm[OFF_W1T + tid * 20 + 17] = b1[tid];
    sm[OFF_B2 + tid] = b2[tid];
    for (int q = tid; q < 4096; q += THREADS) sm[OFF_W3 + q] = W3[q];
    if (tid < 16) sm[OFF_B3 + tid] = b3[tid];

    // ---- RK4 state mapping (phases A/C2): thread t -> sample s=t>>3, comps (i0,i0+1) ----
    const int s  = tid >> 3;
    const int i0 = (tid & 7) << 1;
    const int gid = blockIdx.x * SPC + s;
    float z0a = x[gid * 16 + i0];
    float z0b = x[gid * 16 + i0 + 1];
    sm[OFF_Z + s * 17 + i0]     = z0a;
    sm[OFF_Z + s * 17 + i0 + 1] = z0b;
    float ka = 0.0f, kb = 0.0f;
    float divsum = 0.0f;

    // ---- phase-B micro-tile mapping: warp -> 32-k block; lane = sq*8 + kq ----
    const int kq = lane & 7;          // k group of 4
    const int sq = lane >> 3;         // sample group of 8
    const int k0 = (warp << 5) + (kq << 2);
    const int s0 = sq << 3;           // first of 8 samples
    __syncthreads();

    for (int st = 0; st < 10; ++st) {
        const float tn = (float)st * DT;
#pragma unroll 1
        for (int sub = 0; sub < 4; ++sub) {
            const float te = tn + ((sub == 0) ? 0.0f : ((sub == 3) ? DT : HDT));

            // ======== Phase A: layer 1. warp -> j range, lane -> sample ========
            {
                float zr[16];
#pragma unroll
                for (int i = 0; i < 16; i++) zr[i] = sm[OFF_Z + lane * 17 + i];
                const int jbase = warp << 5;
#pragma unroll 4
                for (int jj = 0; jj < 32; jj++) {
                    const int j = jbase + jj;
                    const float* wr = sm + OFF_W1T + j * 20;
                    float4 w0 = *(const float4*)(wr);
                    float4 w1v = *(const float4*)(wr + 4);
                    float4 w2v = *(const float4*)(wr + 8);
                    float4 w3v = *(const float4*)(wr + 12);
                    float2 tb = *(const float2*)(wr + 16);
                    float a = fmaf(te, tb.x, tb.y);
                    a = fmaf(zr[0],  w0.x, a);  a = fmaf(zr[1],  w0.y, a);
                    a = fmaf(zr[2],  w0.z, a);  a = fmaf(zr[3],  w0.w, a);
                    a = fmaf(zr[4],  w1v.x, a); a = fmaf(zr[5],  w1v.y, a);
                    a = fmaf(zr[6],  w1v.z, a); a = fmaf(zr[7],  w1v.w, a);
                    a = fmaf(zr[8],  w2v.x, a); a = fmaf(zr[9],  w2v.y, a);
                    a = fmaf(zr[10], w2v.z, a); a = fmaf(zr[11], w2v.w, a);
                    a = fmaf(zr[12], w3v.x, a); a = fmaf(zr[13], w3v.y, a);
                    a = fmaf(zr[14], w3v.z, a); a = fmaf(zr[15], w3v.w, a);
                    float e  = __expf(-a);
                    float sg = __fdividef(1.0f, 1.0f + e);
                    float h  = a * sg;                      // silu
                    float d  = fmaf(h, 1.0f - sg, sg);      // silu'
                    hdp[j * 32 + lane] = pack2(h, d);       // interleaved (h,d)
                }
            }
            __syncthreads();

            // ======== Phase B: ONE fused f32x2 GEMM stream ========
            // acc[sp*4+kk] lanes: lo = a2[s,k] (h1·W2), hi = u[s,k] (d1·H)
            ull acc[32];
            {
                const float4 b2v = *(const float4*)(sm + OFF_B2 + k0);
                const ull bi[4] = { pack2(b2v.x, 0.0f), pack2(b2v.y, 0.0f),
                                    pack2(b2v.z, 0.0f), pack2(b2v.w, 0.0f) };
#pragma unroll
                for (int sp = 0; sp < 8; sp++) {
                    acc[sp * 4 + 0] = bi[0]; acc[sp * 4 + 1] = bi[1];
                    acc[sp * 4 + 2] = bi[2]; acc[sp * 4 + 3] = bi[3];
                }
                const ull* wgp = g_WG + k0;
#pragma unroll 1
                for (int jb = 0; jb < 256; jb += 2) {
                    ulonglong2 wA0 = __ldg((const ulonglong2*)(wgp + (jb << 8)));
                    ulonglong2 wA1 = __ldg((const ulonglong2*)(wgp + (jb << 8) + 2));
                    ulonglong2 wB0 = __ldg((const ulonglong2*)(wgp + ((jb + 1) << 8)));
                    ulonglong2 wB1 = __ldg((const ulonglong2*)(wgp + ((jb + 1) << 8) + 2));
#pragma unroll
                    for (int u = 0; u < 2; u++) {
                        const ulonglong2* hp =
                            (const ulonglong2*)(hdp + ((jb + u) << 5) + s0);
                        ulonglong2 h01 = hp[0], h23 = hp[1];
                        ulonglong2 h45 = hp[2], h67 = hp[3];
                        const ull hs[8] = {h01.x, h01.y, h23.x, h23.y,
                                           h45.x, h45.y, h67.x, h67.y};
                        const ull wk[4] = {
                            u ? wB0.x : wA0.x, u ? wB0.y : wA0.y,
                            u ? wB1.x : wA1.x, u ? wB1.y : wA1.y };
#pragma unroll
                        for (int sp = 0; sp < 8; sp++) {
                            acc[sp * 4 + 0] = fma2(hs[sp], wk[0], acc[sp * 4 + 0]);
                            acc[sp * 4 + 1] = fma2(hs[sp], wk[1], acc[sp * 4 + 1]);
                            acc[sp * 4 + 2] = fma2(hs[sp], wk[2], acc[sp * 4 + 2]);
                            acc[sp * 4 + 3] = fma2(hs[sp], wk[3], acc[sp * 4 + 3]);
                        }
                    }
                }
            }

            // ======== Phase C1: silu(a2), div partial dp = sum_k u*silu'(a2) ========
            {
                float dps[8];
#pragma unroll
                for (int sp = 0; sp < 8; sp++) {
                    dps[sp] = 0.0f;
                    float hk[4];
#pragma unroll
                    for (int kk = 0; kk < 4; kk++) {
                        float a, uu;
                        unpack2(acc[sp * 4 + kk], a, uu);
                        float e = __expf(-a);
                        float g = __fdividef(1.0f, 1.0f + e);
                        float h = a * g;
                        float d2 = fmaf(h, 1.0f - g, g);
                        hk[kk] = h;
                        dps[sp] = fmaf(uu, d2, dps[sp]);
                    }
                    acc[sp * 4 + 0] = pack2(hk[0], hk[1]);   // keep h2 packed by k-pair
                    acc[sp * 4 + 1] = pack2(hk[2], hk[3]);
                }
                // reduce each sample's partial over the 8 kq lanes (lane bits 0..2)
#pragma unroll
                for (int sp = 0; sp < 8; sp++) {
                    dps[sp] += __shfl_xor_sync(0xffffffffu, dps[sp], 1);
                    dps[sp] += __shfl_xor_sync(0xffffffffu, dps[sp], 2);
                    dps[sp] += __shfl_xor_sync(0xffffffffu, dps[sp], 4);
                }
                if (kq == 0) {
#pragma unroll
                    for (int sp = 0; sp < 8; sp++)
                        sm[OFF_WD + warp * 32 + s0 + sp] = dps[sp];
                }
            }
            __syncthreads();   // phase-B readers of hd done; WD visible

            // ======== h2 store ([s][256]) + cross-warp div reduce ========
            {
#pragma unroll
                for (int sp = 0; sp < 8; sp++) {
                    ulonglong2 v;
                    v.x = acc[sp * 4 + 0];
                    v.y = acc[sp * 4 + 1];
                    *(ulonglong2*)(sm + OFF_HD + (s0 + sp) * 256 + k0) = v;
                }
                if (tid < 32) {
                    float dv = 0.0f;
#pragma unroll
                    for (int w = 0; w < 8; w++) dv += sm[OFF_WD + w * 32 + tid];
                    sm[OFF_DV + tid] = dv;
                }
            }
            __syncthreads();

            // ======== Phase C2: layer 3 + RK4 update. thread -> (s, i0) ========
            {
                ull fz = pack2(sm[OFF_B3 + i0], sm[OFF_B3 + i0 + 1]);
                const float* h2r = sm + OFF_HD + s * 256;
#pragma unroll 4
                for (int k = 0; k < 256; k += 4) {
                    float4 hq = *(const float4*)(h2r + k);
                    fz = fma2(pack2(hq.x, hq.x), *(const ull*)(sm + OFF_W3 + (k + 0) * 16 + i0), fz);
                    fz = fma2(pack2(hq.y, hq.y), *(const ull*)(sm + OFF_W3 + (k + 1) * 16 + i0), fz);
                    fz = fma2(pack2(hq.z, hq.z), *(const ull*)(sm + OFF_W3 + (k + 2) * 16 + i0), fz);
                    fz = fma2(pack2(hq.w, hq.w), *(const ull*)(sm + OFF_W3 + (k + 3) * 16 + i0), fz);
                }
                float f0, f1;
                unpack2(fz, f0, f1);
                const float wgt = (sub == 1 || sub == 2) ? 2.0f : 1.0f;
                ka = fmaf(wgt, f0, ka);
                kb = fmaf(wgt, f1, kb);
                if ((tid & 7) == 0) divsum = fmaf(wgt, sm[OFF_DV + s], divsum);
                if (sub < 3) {
                    const float c = (sub == 2) ? DT : HDT;
                    sm[OFF_Z + s * 17 + i0]     = fmaf(c, f0, z0a);
                    sm[OFF_Z + s * 17 + i0 + 1] = fmaf(c, f1, z0b);
                } else {
                    z0a = fmaf(DT / 6.0f, ka, z0a);
                    z0b = fmaf(DT / 6.0f, kb, z0b);
                    ka = 0.0f; kb = 0.0f;
                    sm[OFF_Z + s * 17 + i0]     = z0a;
                    sm[OFF_Z + s * 17 + i0 + 1] = z0b;
                }
            }
            __syncthreads();
        }
    }

    // ---- final: logpz - logp1 ----
    float ss = z0a * z0a + z0b * z0b;
    ss += __shfl_xor_sync(0xffffffffu, ss, 1);
    ss += __shfl_xor_sync(0xffffffffu, ss, 2);
    ss += __shfl_xor_sync(0xffffffffu, ss, 4);
    if ((tid & 7) == 0)
        out[gid] = -0.5f * (ss + 16.0f * LOG2PI) + (DT / 6.0f) * divsum;
}

extern "C" void kernel_launch(void* const* d_in, const int* in_sizes, int n_in,
                              void* d_out, int out_size) {
    const float* x  = (const float*)d_in[0];
    const float* W1 = (const float*)d_in[1];
    const float* b1 = (const float*)d_in[2];
    const float* W2 = (const float*)d_in[3];
    const float* b2 = (const float*)d_in[4];
    const float* W3 = (const float*)d_in[5];
    const float* b3 = (const float*)d_in[6];
    float* out = (float*)d_out;

    comp_WG<<<256, 256>>>(W1, W2, W3);

    cudaFuncSetAttribute(cnf_kernel, cudaFuncAttributeMaxDynamicSharedMemorySize,
                         SMEM_BYTES);
    cnf_kernel<<<NBLK, THREADS, SMEM_BYTES>>>(x, W1, b1, W2, b2, W3, b3, out);
}

// round 10
// speedup vs baseline: 1.6969x; 1.0304x over previous
#include <cuda_runtime.h>

typedef unsigned long long ull;

#define THREADS 256
#define SPC     32            // samples per CTA
#define NBLK    256           // 8192 / 32
#define DT      0.1f
#define HDT     0.05f
#define LOG2PI  1.83787706640934548356f

// Interleaved weight matrix: WG[j][k] = (W2[j,k], H[j,k]) packed as f32x2,
// where H[j][k] = W2[j][k] * sum_i W1[i][j]*W3[k][i]  (divergence matrix).
__device__ ull g_WG[256 * 256];

// ---------------- packed f32x2 helpers ----------------
__device__ __forceinline__ ull pack2(float lo, float hi) {
    ull v;
    asm("mov.b64 %0, {%1,%2};" : "=l"(v)
        : "r"(__float_as_uint(lo)), "r"(__float_as_uint(hi)));
    return v;
}
__device__ __forceinline__ void unpack2(ull v, float& lo, float& hi) {
    unsigned a, b;
    asm("mov.b64 {%0,%1}, %2;" : "=r"(a), "=r"(b) : "l"(v));
    lo = __uint_as_float(a); hi = __uint_as_float(b);
}
__device__ __forceinline__ ull fma2(ull a, ull b, ull c) {
    ull d;
    asm("fma.rn.f32x2 %0, %1, %2, %3;" : "=l"(d) : "l"(a), "l"(b), "l"(c));
    return d;
}

// ---------------- shared-memory layout (float offsets) ----------------
#define OFF_W1T 0        // [j][0..15]=W1 z-rows, [16]=W1 t-row, [17]=b1; stride 20 -> 5120
#define OFF_B2  5120     // 256
#define OFF_W3D 5376     // w3 pairs [p][k] ull, row stride 258 ull (516 f) -> 4128 floats
#define OFF_B3  9504     // 16
#define OFF_Z   9520     // z_eval [s*17+i] -> 544
#define OFF_HD  10064    // (h1,d1) ull pairs [j*32 + swz(s)] (16384 f);
                         // ALIASED as h2dup [s][k] ull, row stride 258 ull -> 16512 f
#define OFF_WD  26576    // per-warp div partials [w*32+s] (256)
#define OFF_DV  26832    // div[s] (32)
#define SMEM_FLOATS 26864
#define SMEM_BYTES (SMEM_FLOATS * 4)

// hd-row 16B-chunk swizzle: chunk c (0..15) -> (c & ~3) | ((c & 3) ^ (c >> 2))
// Makes the 4 sq-segment loads bank-disjoint (verified per-q bank bases).

// ---------------- precompute interleaved WG ----------------
__global__ void comp_WG(const float* __restrict__ W1,
                        const float* __restrict__ W2,
                        const float* __restrict__ W3) {
    int j = blockIdx.x;      // 0..255
    int k = threadIdx.x;     // 0..255
    float g = 0.0f;
#pragma unroll
    for (int i = 0; i < 16; i++)
        g = fmaf(W1[i * 256 + j], W3[k * 16 + i], g);
    float w = W2[j * 256 + k];
    g_WG[j * 256 + k] = pack2(w, g * w);
}

// ---------------- main CNF kernel ----------------
__global__ __launch_bounds__(THREADS, 2)
void cnf_kernel(const float* __restrict__ x,
                const float* __restrict__ W1, const float* __restrict__ b1,
                const float* __restrict__ W2, const float* __restrict__ b2,
                const float* __restrict__ W3, const float* __restrict__ b3,
                float* __restrict__ out) {
    extern __shared__ float sm[];
    ull* hdp = (ull*)(sm + OFF_HD);
    const int tid  = threadIdx.x;
    const int lane = tid & 31;
    const int warp = tid >> 5;

    // ---- stage weights into shared ----
#pragma unroll
    for (int i = 0; i < 17; i++)
        sm[OFF_W1T + tid * 20 + i] = W1[i * 256 + tid];
    sm[OFF_W1T + tid * 20 + 17] = b1[tid];
    sm[OFF_B2 + tid] = b2[tid];
    {   // W3 as (2i,2i+1) pairs: w3d[p*258 + k], p = head-pair 0..7
        ull* w3d = (ull*)(sm + OFF_W3D);
        const int p = tid >> 5;
#pragma unroll
        for (int q = 0; q < 8; q++) {
            const int k = lane + (q << 5);
            w3d[p * 258 + k] = pack2(W3[k * 16 + 2 * p], W3[k * 16 + 2 * p + 1]);
        }
    }
    if (tid < 16) sm[OFF_B3 + tid] = b3[tid];

    // ---- RK4 state mapping (phases A/C2): thread t -> sample s=t>>3, comps (i0,i0+1) ----
    const int s  = tid >> 3;
    const int i0 = (tid & 7) << 1;
    const int gid = blockIdx.x * SPC + s;
    float z0a = x[gid * 16 + i0];
    float z0b = x[gid * 16 + i0 + 1];
    sm[OFF_Z + s * 17 + i0]     = z0a;
    sm[OFF_Z + s * 17 + i0 + 1] = z0b;
    float ka = 0.0f, kb = 0.0f;
    float divsum = 0.0f;

    // ---- phase-A hd-store swizzled slot for this lane's sample ----
    const int cA  = lane >> 1;
    const int cAp = (cA & ~3) | ((cA & 3) ^ (cA >> 2));
    const int su  = (cAp << 1) | (lane & 1);          // swizzled ull slot within row

    // ---- phase-B micro-tile mapping: warp -> 32-k block; lane = sq*8 + kq ----
    const int kq = lane & 7;          // k group of 4
    const int sq = lane >> 3;         // sample group of 8
    const int k0 = (warp << 5) + (kq << 2);
    const int s0 = sq << 3;           // first of 8 samples
    // swizzled hd chunk offsets (ull) for q = 0..3
    const int o0 = ((sq << 2) | (0 ^ sq)) << 1;
    const int o1 = ((sq << 2) | (1 ^ sq)) << 1;
    const int o2 = ((sq << 2) | (2 ^ sq)) << 1;
    const int o3 = ((sq << 2) | (3 ^ sq)) << 1;
    __syncthreads();

    for (int st = 0; st < 10; ++st) {
        const float tn = (float)st * DT;
#pragma unroll 1
        for (int sub = 0; sub < 4; ++sub) {
            const float te = tn + ((sub == 0) ? 0.0f : ((sub == 3) ? DT : HDT));

            // ======== Phase A: layer 1. warp -> j range, lane -> sample ========
            {
                float zr[16];
#pragma unroll
                for (int i = 0; i < 16; i++) zr[i] = sm[OFF_Z + lane * 17 + i];
                const int jbase = warp << 5;
#pragma unroll 4
                for (int jj = 0; jj < 32; jj++) {
                    const int j = jbase + jj;
                    const float* wr = sm + OFF_W1T + j * 20;
                    float4 w0 = *(const float4*)(wr);
                    float4 w1v = *(const float4*)(wr + 4);
                    float4 w2v = *(const float4*)(wr + 8);
                    float4 w3v = *(const float4*)(wr + 12);
                    float2 tb = *(const float2*)(wr + 16);
                    float a = fmaf(te, tb.x, tb.y);
                    a = fmaf(zr[0],  w0.x, a);  a = fmaf(zr[1],  w0.y, a);
                    a = fmaf(zr[2],  w0.z, a);  a = fmaf(zr[3],  w0.w, a);
                    a = fmaf(zr[4],  w1v.x, a); a = fmaf(zr[5],  w1v.y, a);
                    a = fmaf(zr[6],  w1v.z, a); a = fmaf(zr[7],  w1v.w, a);
                    a = fmaf(zr[8],  w2v.x, a); a = fmaf(zr[9],  w2v.y, a);
                    a = fmaf(zr[10], w2v.z, a); a = fmaf(zr[11], w2v.w, a);
                    a = fmaf(zr[12], w3v.x, a); a = fmaf(zr[13], w3v.y, a);
                    a = fmaf(zr[14], w3v.z, a); a = fmaf(zr[15], w3v.w, a);
                    float e  = __expf(-a);
                    float sg = __fdividef(1.0f, 1.0f + e);
                    float h  = a * sg;                      // silu
                    float d  = fmaf(h, 1.0f - sg, sg);      // silu'
                    hdp[(j << 5) + su] = pack2(h, d);       // swizzled (h,d)
                }
            }
            __syncthreads();

            // ======== Phase B: ONE fused f32x2 GEMM, weight prefetch 1-ahead ====
            // acc[sp*4+kk] lanes: lo = a2[s,k] (h1·W2), hi = u[s,k] (d1·H)
            ull acc[32];
            {
                const float4 b2v = *(const float4*)(sm + OFF_B2 + k0);
                const ull bi0 = pack2(b2v.x, 0.0f), bi1 = pack2(b2v.y, 0.0f);
                const ull bi2 = pack2(b2v.z, 0.0f), bi3 = pack2(b2v.w, 0.0f);
#pragma unroll
                for (int sp = 0; sp < 8; sp++) {
                    acc[sp * 4 + 0] = bi0; acc[sp * 4 + 1] = bi1;
                    acc[sp * 4 + 2] = bi2; acc[sp * 4 + 3] = bi3;
                }
                const ull* wgp = g_WG + k0;
                ulonglong2 wc0 = __ldg((const ulonglong2*)(wgp));
                ulonglong2 wc1 = __ldg((const ulonglong2*)(wgp + 2));
#pragma unroll 2
                for (int j = 0; j < 256; j++) {
                    const int jn = (j + 1) & 255;
                    ulonglong2 wn0 = __ldg((const ulonglong2*)(wgp + (jn << 8)));
                    ulonglong2 wn1 = __ldg((const ulonglong2*)(wgp + (jn << 8) + 2));
                    const ull* hr = hdp + (j << 5);
                    ulonglong2 hA = *(const ulonglong2*)(hr + o0);
                    ulonglong2 hB = *(const ulonglong2*)(hr + o1);
                    ulonglong2 hC = *(const ulonglong2*)(hr + o2);
                    ulonglong2 hD = *(const ulonglong2*)(hr + o3);
                    const ull hs[8] = {hA.x, hA.y, hB.x, hB.y,
                                       hC.x, hC.y, hD.x, hD.y};
#pragma unroll
                    for (int sp = 0; sp < 8; sp++) {
                        acc[sp * 4 + 0] = fma2(hs[sp], wc0.x, acc[sp * 4 + 0]);
                        acc[sp * 4 + 1] = fma2(hs[sp], wc0.y, acc[sp * 4 + 1]);
                        acc[sp * 4 + 2] = fma2(hs[sp], wc1.x, acc[sp * 4 + 2]);
                        acc[sp * 4 + 3] = fma2(hs[sp], wc1.y, acc[sp * 4 + 3]);
                    }
                    wc0 = wn0; wc1 = wn1;
                }
            }

            // ======== Phase C1: silu(a2), div partial dp = sum_k u*silu'(a2) ====
            // acc is rewritten as duplicate-packed h2: acc[sp*4+kk] = (h,h)
            {
                float dps[8];
#pragma unroll
                for (int sp = 0; sp < 8; sp++) {
                    dps[sp] = 0.0f;
#pragma unroll
                    for (int kk = 0; kk < 4; kk++) {
                        float a, uu;
                        unpack2(acc[sp * 4 + kk], a, uu);
                        float e = __expf(-a);
                        float g = __fdividef(1.0f, 1.0f + e);
                        float h = a * g;
                        float d2 = fmaf(h, 1.0f - g, g);
                        dps[sp] = fmaf(uu, d2, dps[sp]);
                        acc[sp * 4 + kk] = pack2(h, h);      // dup-packed h2
                    }
                }
                // reduce each sample's partial over the 8 kq lanes (lane bits 0..2)
#pragma unroll
                for (int sp = 0; sp < 8; sp++) {
                    dps[sp] += __shfl_xor_sync(0xffffffffu, dps[sp], 1);
                    dps[sp] += __shfl_xor_sync(0xffffffffu, dps[sp], 2);
                    dps[sp] += __shfl_xor_sync(0xffffffffu, dps[sp], 4);
                }
                if (kq == 0) {
#pragma unroll
                    for (int sp = 0; sp < 8; sp++)
                        sm[OFF_WD + warp * 32 + s0 + sp] = dps[sp];
                }
            }
            __syncthreads();   // phase-B readers of hd done; WD visible

            // ======== h2dup store ([s][258-ull rows]) + cross-warp div reduce ====
            {
                ull* h2w = (ull*)(sm + OFF_HD);
#pragma unroll
                for (int sp = 0; sp < 8; sp++) {
                    ull* r = h2w + (s0 + sp) * 258 + k0;
                    ulonglong2 v0, v1;
                    v0.x = acc[sp * 4 + 0]; v0.y = acc[sp * 4 + 1];
                    v1.x = acc[sp * 4 + 2]; v1.y = acc[sp * 4 + 3];
                    *(ulonglong2*)(r)     = v0;
                    *(ulonglong2*)(r + 2) = v1;
                }
                if (tid < 32) {
                    float dv = 0.0f;
#pragma unroll
                    for (int w = 0; w < 8; w++) dv += sm[OFF_WD + w * 32 + tid];
                    sm[OFF_DV + tid] = dv;
                }
            }
            __syncthreads();

            // ======== Phase C2: layer 3 (pure fma2 stream) + RK4 update =========
            {
                const ull* h2r = (const ull*)(sm + OFF_HD) + s * 258;
                const ull* w3r = (const ull*)(sm + OFF_W3D) + (tid & 7) * 258;
                ull f0a = pack2(sm[OFF_B3 + i0], sm[OFF_B3 + i0 + 1]);
                ull f1a = 0ULL, f2a = 0ULL, f3a = 0ULL;
#pragma unroll 4
                for (int k = 0; k < 256; k += 4) {
                    ulonglong2 hh0 = *(const ulonglong2*)(h2r + k);
                    ulonglong2 ww0 = *(const ulonglong2*)(w3r + k);
                    ulonglong2 hh1 = *(const ulonglong2*)(h2r + k + 2);
                    ulonglong2 ww1 = *(const ulonglong2*)(w3r + k + 2);
                    f0a = fma2(hh0.x, ww0.x, f0a);
                    f1a = fma2(hh0.y, ww0.y, f1a);
                    f2a = fma2(hh1.x, ww1.x, f2a);
                    f3a = fma2(hh1.y, ww1.y, f3a);
                }
                float p0, p1, q0, q1, r0, r1, t0, t1;
                unpack2(f0a, p0, p1); unpack2(f1a, q0, q1);
                unpack2(f2a, r0, r1); unpack2(f3a, t0, t1);
                float f0 = (p0 + q0) + (r0 + t0);
                float f1 = (p1 + q1) + (r1 + t1);
                const float wgt = (sub == 1 || sub == 2) ? 2.0f : 1.0f;
                ka = fmaf(wgt, f0, ka);
                kb = fmaf(wgt, f1, kb);
                if ((tid & 7) == 0) divsum = fmaf(wgt, sm[OFF_DV + s], divsum);
                if (sub < 3) {
                    const float c = (sub == 2) ? DT : HDT;
                    sm[OFF_Z + s * 17 + i0]     = fmaf(c, f0, z0a);
                    sm[OFF_Z + s * 17 + i0 + 1] = fmaf(c, f1, z0b);
                } else {
                    z0a = fmaf(DT / 6.0f, ka, z0a);
                    z0b = fmaf(DT / 6.0f, kb, z0b);
                    ka = 0.0f; kb = 0.0f;
                    sm[OFF_Z + s * 17 + i0]     = z0a;
                    sm[OFF_Z + s * 17 + i0 + 1] = z0b;
                }
            }
            __syncthreads();
        }
    }

    // ---- final: logpz - logp1 ----
    float ss = z0a * z0a + z0b * z0b;
    ss += __shfl_xor_sync(0xffffffffu, ss, 1);
    ss += __shfl_xor_sync(0xffffffffu, ss, 2);
    ss += __shfl_xor_sync(0xffffffffu, ss, 4);
    if ((tid & 7) == 0)
        out[gid] = -0.5f * (ss + 16.0f * LOG2PI) + (DT / 6.0f) * divsum;
}

extern "C" void kernel_launch(void* const* d_in, const int* in_sizes, int n_in,
                              void* d_out, int out_size) {
    const float* x  = (const float*)d_in[0];
    const float* W1 = (const float*)d_in[1];
    const float* b1 = (const float*)d_in[2];
    const float* W2 = (const float*)d_in[3];
    const float* b2 = (const float*)d_in[4];
    const float* W3 = (const float*)d_in[5];
    const float* b3 = (const float*)d_in[6];
    float* out = (float*)d_out;

    comp_WG<<<256, 256>>>(W1, W2, W3);

    cudaFuncSetAttribute(cnf_kernel, cudaFuncAttributeMaxDynamicSharedMemorySize,
                         SMEM_BYTES);
    cnf_kernel<<<NBLK, THREADS, SMEM_BYTES>>>(x, W1, b1, W2, b2, W3, b3, out);
}